// round 15
// baseline (speedup 1.0000x reference)
#include <cuda_runtime.h>
#include <cuda_fp16.h>
#include <math.h>
#include <stdint.h>

// Problem constants
#define BB 4
#define TT 2048
#define INF_ 64
#define DD 512
#define HH 8
#define DH 64
#define FF_ 2048
#define LL 4
#define LAT 128
#define PAST 40
#define FUT 120
#define ROWS (BB*TT)          // 8192
#define EPS 1e-5f

// ---------------- scratch (device globals; no allocation allowed) ----------
__device__ float   g_x   [ROWS * DD];        // residual master (f32)
__device__ float   g_pool[BB * DD];
__device__ float   g_pp  [BB * 32 * DD];
__device__ float   g_h   [BB * 2 * LAT];
__device__ __half  g_xh  [ROWS * DD];        // x (half mirror, GEMM A)
__device__ __half  g_tmph[ROWS * DD];        // pre-LN sums (half)
__device__ __half  g_qkvh[ROWS * 3 * DD];    // qkv (half)
__device__ __half  g_ctxh[ROWS * DD];        // attention output (half)
__device__ __half  g_ffh [ROWS * FF_];       // ff1 output (half)
__device__ __half  g_fh  [ROWS * INF_];      // feats (half)
__device__ __half  g_wt  [12615680];         // weights transposed [n][k], half

// half-element offsets into g_wt
#define WT_PROJ 0
#define WT_QKV  32768
#define WT_OUT  3178496
#define WT_FF1  4227072
#define WT_FF2  8421376

// ---------------- helpers ---------------------------------------------------
__device__ __forceinline__ uint32_t pack_h2f(float lo, float hi) {
    __half2 h = __floats2half2_rn(lo, hi);
    return *reinterpret_cast<uint32_t*>(&h);
}
__device__ __forceinline__ uint32_t sptr(const void* p) {
    return (uint32_t)__cvta_generic_to_shared(p);
}
__device__ __forceinline__ void cpa16(uint32_t dst, const void* src) {
    asm volatile("cp.async.cg.shared.global [%0], [%1], 16;\n" :: "r"(dst), "l"(src));
}
#define CP_COMMIT() asm volatile("cp.async.commit_group;\n")
#define CP_WAIT(n)  asm volatile("cp.async.wait_group %0;\n" :: "n"(n))

#define MMA_F16(d0,d1,d2,d3,a0,a1,a2,a3,b0,b1)                               \
    asm volatile("mma.sync.aligned.m16n8k16.row.col.f32.f16.f16.f32 "        \
        "{%0,%1,%2,%3},{%4,%5,%6,%7},{%8,%9},{%0,%1,%2,%3};"                 \
        : "+f"(d0),"+f"(d1),"+f"(d2),"+f"(d3)                                \
        : "r"(a0),"r"(a1),"r"(a2),"r"(a3),"r"(b0),"r"(b1))

#define LDMATRIX_X4(r0,r1,r2,r3,addr)                                        \
    asm volatile("ldmatrix.sync.aligned.m8n8.x4.shared.b16 {%0,%1,%2,%3}, [%4];" \
        : "=r"(r0),"=r"(r1),"=r"(r2),"=r"(r3) : "r"(addr))

#define LDMATRIX_X2(r0,r1,addr)                                              \
    asm volatile("ldmatrix.sync.aligned.m8n8.x2.shared.b16 {%0,%1}, [%2];"   \
        : "=r"(r0),"=r"(r1) : "r"(addr))

// ---------------- weight transpose-pack: Wt[n][k] = half(W[k][n]) -----------
__global__ void pack_wt(const float* __restrict__ W, __half* __restrict__ Wt,
                        int K, int N)
{
    __shared__ float t[32][33];
    const float* Wz = W + (size_t)blockIdx.z * K * N;
    __half* Wtz = Wt + (size_t)blockIdx.z * K * N;
    const int n0 = blockIdx.x * 32, k0 = blockIdx.y * 32;
    const int x = threadIdx.x, y = threadIdx.y;
#pragma unroll
    for (int i = 0; i < 32; i += 8)
        t[y + i][x] = Wz[(size_t)(k0 + y + i) * N + n0 + x];
    __syncthreads();
#pragma unroll
    for (int i = 0; i < 32; i += 8)
        Wtz[(size_t)(n0 + y + i) * K + k0 + x] = __float2half_rn(t[x][y + i]);
}

// ---------------- f32 -> half convert ---------------------------------------
__global__ void conv_half(const float* __restrict__ in, __half* __restrict__ out,
                          int n2)
{
    const int i = blockIdx.x * 256 + threadIdx.x;
    if (i >= n2) return;
    const float2 v = ((const float2*)in)[i];
    ((__half2*)out)[i] = __floats2half2_rn(v.x, v.y);
}

// ---------------- FP16 GEMM, cp.async 4-stage, ldmatrix A+B frags -----------
// C[M,N] = A[M,K] @ W[K,N] + bias, W given transposed half: Bt[n][k].
// BM=BN=128, BK=32, 8 warps. Both smem tiles [128][20] words, stride-20.
// EPI: 1 = +bias, relu -> Ch ; 2 = +bias+posenc(f32) -> Ch AND Cf ;
//      3 = +bias -> Ch ; 6 = +bias + residf(f32) -> Ch
#define P2 20
#define STG (128 * P2)                     // words per operand stage
#define GH_SMEM (4 * 2 * STG * 4)          // 81920 B

template <int EPI>
__global__ __launch_bounds__(256, 2)
void gemm_h(const __half* __restrict__ A, const __half* __restrict__ Bt,
            const float* __restrict__ bias, const float* __restrict__ extraf,
            const float* __restrict__ residf, __half* __restrict__ Ch,
            float* __restrict__ Cf, int N, int K)
{
    extern __shared__ uint32_t smw[];
    uint32_t* As = smw;                    // [4][128][20]
    uint32_t* Bs = smw + 4 * STG;          // [4][128][20]

    const int tid  = threadIdx.x;
    const int wid  = tid >> 5, lane = tid & 31;
    const int g    = lane >> 2, c = lane & 3;
    const int wm   = (wid >> 2) * 64;
    const int wn   = (wid & 3) * 32;
    const int brow = blockIdx.y * 128, bcol = blockIdx.x * 128;

    const int arow = tid >> 1, ach = tid & 1;

    const __half* Ag = A  + (size_t)(brow + arow) * K + ach * 16;
    const __half* Bg = Bt + (size_t)(bcol + arow) * K + ach * 16;

    const uint32_t sA = sptr(As) + (uint32_t)(arow * P2 + ach * 8) * 4u;
    const uint32_t sB = sptr(Bs) + (uint32_t)(arow * P2 + ach * 8) * 4u;
    const uint32_t lmoffA = (uint32_t)((lane & 15) * P2 + (lane >> 4) * 4) * 4u;
    const uint32_t lmoffB = (uint32_t)((lane & 7) * P2 + ((lane >> 3) & 1) * 4) * 4u;

    float acc[4][4][4];
#pragma unroll
    for (int i = 0; i < 4; i++)
#pragma unroll
        for (int j = 0; j < 4; j++)
#pragma unroll
            for (int r = 0; r < 4; r++) acc[i][j][r] = 0.f;

    const int nk = K >> 5;

    auto issue = [&](int i, int sl) {
        const __half* ga = Ag + (size_t)i * 32;
        cpa16(sA + sl * STG * 4, ga);
        cpa16(sA + sl * STG * 4 + 16, ga + 8);
        const __half* gb = Bg + (size_t)i * 32;
        cpa16(sB + sl * STG * 4, gb);
        cpa16(sB + sl * STG * 4 + 16, gb + 8);
        CP_COMMIT();
    };

    issue(0, 0);
    if (nk > 1) issue(1, 1);
    if (nk > 2) issue(2, 2);
    if (nk > 2)      CP_WAIT(2);
    else if (nk > 1) CP_WAIT(1);
    else             CP_WAIT(0);
    __syncthreads();

    for (int s = 0; s < nk; s++) {
        if (s + 3 < nk) issue(s + 3, (s + 3) & 3);

        const int sl = s & 3;
        const uint32_t aBase = sptr(As) + (uint32_t)(sl * STG) * 4u + lmoffA;
        const uint32_t bBase = sptr(Bs) + (uint32_t)(sl * STG) * 4u + lmoffB;
#pragma unroll
        for (int kk = 0; kk < 2; kk++) {
            uint32_t af[4][4];
#pragma unroll
            for (int mt = 0; mt < 4; mt++) {
                const uint32_t addr = aBase
                    + (uint32_t)(((wm + mt * 16) * P2 + kk * 8) * 4);
                LDMATRIX_X4(af[mt][0], af[mt][1], af[mt][2], af[mt][3], addr);
            }
            uint32_t bf[4][2];
#pragma unroll
            for (int nt = 0; nt < 4; nt++) {
                const uint32_t addr = bBase
                    + (uint32_t)(((wn + nt * 8) * P2 + kk * 8) * 4);
                LDMATRIX_X2(bf[nt][0], bf[nt][1], addr);
            }
#pragma unroll
            for (int mt = 0; mt < 4; mt++)
#pragma unroll
                for (int nt = 0; nt < 4; nt++)
                    MMA_F16(acc[mt][nt][0], acc[mt][nt][1], acc[mt][nt][2], acc[mt][nt][3],
                            af[mt][0], af[mt][1], af[mt][2], af[mt][3],
                            bf[nt][0], bf[nt][1]);
        }

        if (s + 1 < nk) {
            if (s + 3 < nk)      CP_WAIT(2);
            else if (s + 2 < nk) CP_WAIT(1);
            else                 CP_WAIT(0);
            __syncthreads();
        }
    }

    // epilogue: frag (row g/g+8, col 2c/2c+1)
#pragma unroll
    for (int mt = 0; mt < 4; mt++) {
#pragma unroll
        for (int nt = 0; nt < 4; nt++) {
            const int col = bcol + wn + nt * 8 + 2 * c;
            const float b0 = bias[col], b1 = bias[col + 1];
#pragma unroll
            for (int half = 0; half < 2; half++) {
                const int row = brow + wm + mt * 16 + g + half * 8;
                float v0 = acc[mt][nt][half * 2 + 0] + b0;
                float v1 = acc[mt][nt][half * 2 + 1] + b1;
                if (EPI == 1) {
                    v0 = fmaxf(v0, 0.f); v1 = fmaxf(v1, 0.f);
                } else if (EPI == 2) {
                    const int t = row & (TT - 1);
                    const float2 p = *(const float2*)(extraf + (size_t)t * N + col);
                    v0 += p.x; v1 += p.y;
                    float2 o; o.x = v0; o.y = v1;
                    *(float2*)(Cf + (size_t)row * N + col) = o;
                } else if (EPI == 6) {
                    const float2 r = *(const float2*)(residf + (size_t)row * N + col);
                    v0 += r.x; v1 += r.y;
                }
                *(__half2*)(Ch + (size_t)row * N + col) = __floats2half2_rn(v0, v1);
            }
        }
    }
}

// ---------------- banded flash attention, full fp16 --------------------------
#define KVPH 72
#define ABUFH (64 * KVPH)
#define ATTN_SMEM (4 * ABUFH * 2)    // 36864 B

__global__ __launch_bounds__(256, 2)
void attn_h(const __half* __restrict__ qkvh, __half* __restrict__ ctxh)
{
    extern __shared__ __half smh[];
    __half* Ks = smh;
    __half* Vs = smh + 2 * ABUFH;

    const int blk = blockIdx.x;
    const int qt = blk & 15;
    const int h  = (blk >> 4) & 7;
    const int b  = blk >> 7;
    const int q0 = qt * 128;

    const int tid = threadIdx.x, wid = tid >> 5, lane = tid & 31;
    const int g = lane >> 2, c = lane & 3;
    const int w0 = q0 + wid * 16;
    const int r0 = w0 + g, r1 = r0 + 8;

    uint32_t qa[4][4];
    {
        const uint32_t* qlo = (const uint32_t*)(qkvh + (size_t)(b * TT + r0) * 1536 + h * 64);
        const uint32_t* qhi = (const uint32_t*)(qkvh + (size_t)(b * TT + r1) * 1536 + h * 64);
#pragma unroll
        for (int kt = 0; kt < 4; kt++) {
            qa[kt][0] = qlo[kt * 8 + c];
            qa[kt][1] = qhi[kt * 8 + c];
            qa[kt][2] = qlo[kt * 8 + c + 4];
            qa[kt][3] = qhi[kt * 8 + c + 4];
        }
    }

    float oacc[8][4];
#pragma unroll
    for (int nt = 0; nt < 8; nt++)
#pragma unroll
        for (int e = 0; e < 4; e++) oacc[nt][e] = 0.f;

    float m0 = -INFINITY, m1 = -INFINITY, l0 = 0.f, l1 = 0.f;
    const float scale = 0.125f;

    int csv[5]; int ncs = 0;
    const int offs[5] = {-64, 0, 64, 128, 192};
#pragma unroll
    for (int i = 0; i < 5; i++) {
        const int cs = q0 + offs[i];
        if (cs >= 0 && cs < TT) csv[ncs++] = cs;
    }

    const int lrow  = (tid >> 1) & 63;
    const int isv   = tid >> 7;
    const int lhalf = tid & 1;
    const uint32_t ldst0 = sptr((isv ? Vs : Ks) + lrow * KVPH + lhalf * 32);
    const size_t lsrc_off = (size_t)512 + (size_t)isv * 512 + h * 64 + lhalf * 32;

    {
        const __half* src = qkvh + (size_t)(b * TT + csv[0] + lrow) * 1536 + lsrc_off;
#pragma unroll
        for (int i = 0; i < 4; i++) cpa16(ldst0 + i * 16, src + i * 8);
        CP_COMMIT();
    }

    for (int ci = 0; ci < ncs; ci++) {
        CP_WAIT(0);
        __syncthreads();

        if (ci + 1 < ncs) {
            const uint32_t dst = ldst0 + ((ci + 1) & 1) * ABUFH * 2;
            const __half* src = qkvh + (size_t)(b * TT + csv[ci + 1] + lrow) * 1536 + lsrc_off;
#pragma unroll
            for (int i = 0; i < 4; i++) cpa16(dst + i * 16, src + i * 8);
            CP_COMMIT();
        }

        const int cs = csv[ci];
        const int lo_key = max(cs, w0 - PAST);
        const int hi_key = min(cs + 63, w0 + 15 + FUT);
        if (lo_key > hi_key) continue;
        const int ntlo = (lo_key - cs) >> 3;
        const int nthi = (hi_key - cs) >> 3;

        const __half* Kb = Ks + (ci & 1) * ABUFH;
        const __half* Vb = Vs + (ci & 1) * ABUFH;

        float sacc[8][4];
#pragma unroll
        for (int nt = 0; nt < 8; nt++) {
            sacc[nt][0] = 0.f; sacc[nt][1] = 0.f;
            sacc[nt][2] = 0.f; sacc[nt][3] = 0.f;
        }
#pragma unroll
        for (int nt = 0; nt < 8; nt++) {
            if (nt < ntlo || nt > nthi) continue;
            const __half* krow = Kb + (nt * 8 + g) * KVPH;
#pragma unroll
            for (int kt = 0; kt < 4; kt++) {
                const uint32_t b0 = *(const uint32_t*)(krow + kt * 16 + 2 * c);
                const uint32_t b1 = *(const uint32_t*)(krow + kt * 16 + 2 * c + 8);
                MMA_F16(sacc[nt][0], sacc[nt][1], sacc[nt][2], sacc[nt][3],
                        qa[kt][0], qa[kt][1], qa[kt][2], qa[kt][3], b0, b1);
            }
        }

        float mx0 = -INFINITY, mx1 = -INFINITY;
#pragma unroll
        for (int nt = 0; nt < 8; nt++) {
            if (nt < ntlo || nt > nthi) continue;
            const int j0 = cs + nt * 8 + 2 * c;
            const int j1 = j0 + 1;
            float v;
            v = sacc[nt][0] * scale;
            v = (j0 >= r0 - PAST && j0 <= r0 + FUT) ? v : -INFINITY;
            sacc[nt][0] = v; mx0 = fmaxf(mx0, v);
            v = sacc[nt][1] * scale;
            v = (j1 >= r0 - PAST && j1 <= r0 + FUT) ? v : -INFINITY;
            sacc[nt][1] = v; mx0 = fmaxf(mx0, v);
            v = sacc[nt][2] * scale;
            v = (j0 >= r1 - PAST && j0 <= r1 + FUT) ? v : -INFINITY;
            sacc[nt][2] = v; mx1 = fmaxf(mx1, v);
            v = sacc[nt][3] * scale;
            v = (j1 >= r1 - PAST && j1 <= r1 + FUT) ? v : -INFINITY;
            sacc[nt][3] = v; mx1 = fmaxf(mx1, v);
        }
        mx0 = fmaxf(mx0, __shfl_xor_sync(0xffffffffu, mx0, 1));
        mx0 = fmaxf(mx0, __shfl_xor_sync(0xffffffffu, mx0, 2));
        mx1 = fmaxf(mx1, __shfl_xor_sync(0xffffffffu, mx1, 1));
        mx1 = fmaxf(mx1, __shfl_xor_sync(0xffffffffu, mx1, 2));

        const float mn0 = fmaxf(m0, mx0);
        const float mn1 = fmaxf(m1, mx1);
        const float rf0 = __expf(fmaxf(m0 - mn0, -88.f));
        const float rf1 = __expf(fmaxf(m1 - mn1, -88.f));
        m0 = mn0; m1 = mn1;

        float ps0 = 0.f, ps1 = 0.f;
#pragma unroll
        for (int nt = 0; nt < 8; nt++) {
            if (nt < ntlo || nt > nthi) continue;
            const float p00 = __expf(fmaxf(sacc[nt][0] - mn0, -88.f));
            const float p01 = __expf(fmaxf(sacc[nt][1] - mn0, -88.f));
            const float p10 = __expf(fmaxf(sacc[nt][2] - mn1, -88.f));
            const float p11 = __expf(fmaxf(sacc[nt][3] - mn1, -88.f));
            ps0 += p00 + p01;
            ps1 += p10 + p11;
            sacc[nt][0] = p00; sacc[nt][1] = p01;
            sacc[nt][2] = p10; sacc[nt][3] = p11;
        }
        ps0 += __shfl_xor_sync(0xffffffffu, ps0, 1);
        ps0 += __shfl_xor_sync(0xffffffffu, ps0, 2);
        ps1 += __shfl_xor_sync(0xffffffffu, ps1, 1);
        ps1 += __shfl_xor_sync(0xffffffffu, ps1, 2);
        l0 = l0 * rf0 + ps0;
        l1 = l1 * rf1 + ps1;

#pragma unroll
        for (int nt = 0; nt < 8; nt++) {
            oacc[nt][0] *= rf0; oacc[nt][1] *= rf0;
            oacc[nt][2] *= rf1; oacc[nt][3] *= rf1;
        }

#pragma unroll
        for (int kp = 0; kp < 4; kp++) {
            const int nt0 = 2 * kp, nt1 = 2 * kp + 1;
            if (nt1 < ntlo || nt0 > nthi) continue;
            const uint32_t a0 = pack_h2f(sacc[nt0][0], sacc[nt0][1]);
            const uint32_t a1 = pack_h2f(sacc[nt0][2], sacc[nt0][3]);
            const uint32_t a2 = pack_h2f(sacc[nt1][0], sacc[nt1][1]);
            const uint32_t a3 = pack_h2f(sacc[nt1][2], sacc[nt1][3]);
            const __half* v0r = Vb + (kp * 16 + 2 * c) * KVPH;
            const __half* v1r = v0r + KVPH;
            const __half* v8r = v0r + 8 * KVPH;
            const __half* v9r = v8r + KVPH;
#pragma unroll
            for (int nt = 0; nt < 8; nt++) {
                const int n = nt * 8 + g;
                const uint32_t b0 = *reinterpret_cast<const uint32_t*>(
                    &__halves2half2(v0r[n], v1r[n]));
                const uint32_t b1 = *reinterpret_cast<const uint32_t*>(
                    &__halves2half2(v8r[n], v9r[n]));
                MMA_F16(oacc[nt][0], oacc[nt][1], oacc[nt][2], oacc[nt][3],
                        a0, a1, a2, a3, b0, b1);
            }
        }
    }

    const float inv0 = 1.f / l0, inv1 = 1.f / l1;
#pragma unroll
    for (int nt = 0; nt < 8; nt++) {
        const int col = h * 64 + nt * 8 + 2 * c;
        *(__half2*)(ctxh + (size_t)(b * TT + r0) * DD + col) =
            __floats2half2_rn(oacc[nt][0] * inv0, oacc[nt][1] * inv0);
        *(__half2*)(ctxh + (size_t)(b * TT + r1) * DD + col) =
            __floats2half2_rn(oacc[nt][2] * inv1, oacc[nt][3] * inv1);
    }
}

// ---------------- LayerNorm on half input ------------------------------------
// FIN = 0: write f32 outf + half outh ; FIN = 1: write f32 outf only
template <int FIN>
__global__ __launch_bounds__(128)
void ln_h(const __half* __restrict__ xin,
          const float* __restrict__ s, const float* __restrict__ bta,
          float* __restrict__ outf, __half* __restrict__ outh)
{
    const int row = blockIdx.x;
    const int tid = threadIdx.x;
    const __half2* xrow = (const __half2*)(xin + (size_t)row * DD);
    float2 v[2];
    float sum = 0.f, sq = 0.f;
#pragma unroll
    for (int i = 0; i < 2; i++) {
        const float2 f = __half22float2(xrow[tid + i * 128]);
        v[i] = f;
        sum += f.x + f.y;
        sq  += f.x * f.x + f.y * f.y;
    }
    __shared__ float rs[8];
#pragma unroll
    for (int off = 16; off > 0; off >>= 1) {
        sum += __shfl_xor_sync(0xffffffffu, sum, off);
        sq  += __shfl_xor_sync(0xffffffffu, sq,  off);
    }
    if ((tid & 31) == 0) { rs[tid >> 5] = sum; rs[4 + (tid >> 5)] = sq; }
    __syncthreads();
    sum = rs[0] + rs[1] + rs[2] + rs[3];
    sq  = rs[4] + rs[5] + rs[6] + rs[7];
    const float mean = sum * (1.f / DD);
    const float var  = sq * (1.f / DD) - mean * mean;
    const float inv  = rsqrtf(var + EPS);
#pragma unroll
    for (int i = 0; i < 2; i++) {
        const int cw = tid + i * 128;
        const int c0 = 2 * cw;
        const float o0 = (v[i].x - mean) * inv * s[c0]     + bta[c0];
        const float o1 = (v[i].y - mean) * inv * s[c0 + 1] + bta[c0 + 1];
        float2 o; o.x = o0; o.y = o1;
        *(float2*)(outf + (size_t)row * DD + c0) = o;
        if (!FIN)
            ((__half2*)(outh + (size_t)row * DD))[cw] = __floats2half2_rn(o0, o1);
    }
}

// ---------------- mean pool (two-stage) -------------------------------------
__global__ void pool_partial(const float* __restrict__ emb, float* __restrict__ pp)
{
    const int b = blockIdx.x >> 5, ch = blockIdx.x & 31;
    const int d = threadIdx.x;
    float s = 0.f;
    const int t0 = ch * 64;
    for (int t = t0; t < t0 + 64; t++)
        s += emb[((size_t)(b * TT + t)) * DD + d];
    pp[(size_t)blockIdx.x * DD + d] = s;
}

__global__ void pool_reduce(const float* __restrict__ pp, float* __restrict__ p)
{
    const int b = blockIdx.x, d = threadIdx.x;
    float s = 0.f;
    for (int ch = 0; ch < 32; ch++)
        s += pp[(size_t)(b * 32 + ch) * DD + d];
    p[b * DD + d] = s * (1.f / TT);
}

// ---------------- tiny dense layer (heads) ----------------------------------
__global__ void small_linear(const float* __restrict__ in, const float* __restrict__ W,
                             const float* __restrict__ bias, float* __restrict__ out,
                             int K, int N, int relu)
{
    const int b = blockIdx.x, n = threadIdx.x;
    if (n >= N) return;
    float sum = bias[n];
    for (int k = 0; k < K; k++)
        sum = fmaf(in[b * K + k], W[(size_t)k * N + n], sum);
    if (relu) sum = fmaxf(sum, 0.f);
    out[b * N + n] = sum;
}

// ---------------- launch -----------------------------------------------------
extern "C" void kernel_launch(void* const* d_in, const int* in_sizes, int n_in,
                              void* d_out, int out_size)
{
    const float* feats  = (const float*)d_in[0];
    const float* projW  = (const float*)d_in[1];
    const float* projB  = (const float*)d_in[2];
    const float* posenc = (const float*)d_in[3];
    const float* qkvW   = (const float*)d_in[4];
    const float* qkvB   = (const float*)d_in[5];
    const float* outW   = (const float*)d_in[6];
    const float* outB   = (const float*)d_in[7];
    const float* ln1s   = (const float*)d_in[8];
    const float* ln1b   = (const float*)d_in[9];
    const float* ff1W   = (const float*)d_in[10];
    const float* ff1B   = (const float*)d_in[11];
    const float* ff2W   = (const float*)d_in[12];
    const float* ff2B   = (const float*)d_in[13];
    const float* ln2s   = (const float*)d_in[14];
    const float* ln2b   = (const float*)d_in[15];
    const float* mu1W   = (const float*)d_in[16];
    const float* mu1B   = (const float*)d_in[17];
    const float* mu2W   = (const float*)d_in[18];
    const float* mu2B   = (const float*)d_in[19];
    const float* lv1W   = (const float*)d_in[20];
    const float* lv1B   = (const float*)d_in[21];
    const float* lv2W   = (const float*)d_in[22];
    const float* lv2B   = (const float*)d_in[23];

    float *px, *ppool, *ppp, *ph;
    __half *pxh, *ptmph, *pqkvh, *pctxh, *pffh, *pfh, *pwt;
    cudaGetSymbolAddress((void**)&px,    g_x);
    cudaGetSymbolAddress((void**)&ppool, g_pool);
    cudaGetSymbolAddress((void**)&ppp,   g_pp);
    cudaGetSymbolAddress((void**)&ph,    g_h);
    cudaGetSymbolAddress((void**)&pxh,   g_xh);
    cudaGetSymbolAddress((void**)&ptmph, g_tmph);
    cudaGetSymbolAddress((void**)&pqkvh, g_qkvh);
    cudaGetSymbolAddress((void**)&pctxh, g_ctxh);
    cudaGetSymbolAddress((void**)&pffh,  g_ffh);
    cudaGetSymbolAddress((void**)&pfh,   g_fh);
    cudaGetSymbolAddress((void**)&pwt,   g_wt);

    cudaFuncSetAttribute(gemm_h<1>, cudaFuncAttributeMaxDynamicSharedMemorySize, GH_SMEM);
    cudaFuncSetAttribute(gemm_h<2>, cudaFuncAttributeMaxDynamicSharedMemorySize, GH_SMEM);
    cudaFuncSetAttribute(gemm_h<3>, cudaFuncAttributeMaxDynamicSharedMemorySize, GH_SMEM);
    cudaFuncSetAttribute(gemm_h<6>, cudaFuncAttributeMaxDynamicSharedMemorySize, GH_SMEM);
    cudaFuncSetAttribute(attn_h,    cudaFuncAttributeMaxDynamicSharedMemorySize, ATTN_SMEM);

    float* emb = (float*)d_out;
    float* mu  = emb + (size_t)ROWS * DD;
    float* lv  = mu + BB * LAT;

    // transpose-pack weights to half [n][k] + convert feats
    {
        dim3 blk(32, 8);
        pack_wt<<<dim3(16, 2, 1),  blk>>>(projW, pwt + WT_PROJ, 64, 512);
        pack_wt<<<dim3(48, 16, 4), blk>>>(qkvW,  pwt + WT_QKV,  512, 1536);
        pack_wt<<<dim3(16, 16, 4), blk>>>(outW,  pwt + WT_OUT,  512, 512);
        pack_wt<<<dim3(64, 16, 4), blk>>>(ff1W,  pwt + WT_FF1,  512, 2048);
        pack_wt<<<dim3(16, 64, 4), blk>>>(ff2W,  pwt + WT_FF2,  2048, 512);
    }
    conv_half<<<(ROWS * INF_ / 2 + 255) / 256, 256>>>(feats, pfh, ROWS * INF_ / 2);

    // x = feats @ projW + projB + posenc (f32 px + half pxh)
    gemm_h<2><<<dim3(4, 64), 256, GH_SMEM>>>(pfh, pwt + WT_PROJ, projB, posenc,
                                             nullptr, pxh, px, 512, 64);

    for (int l = 0; l < LL; l++) {
        gemm_h<3><<<dim3(12, 64), 256, GH_SMEM>>>(pxh, pwt + WT_QKV + (size_t)l * 786432,
                                                  qkvB + l * 3 * DD, nullptr, nullptr,
                                                  pqkvh, nullptr, 1536, 512);
        attn_h<<<BB * HH * 16, 256, ATTN_SMEM>>>(pqkvh, pctxh);
        // tmph = ctx @ outW + outB + x(f32)
        gemm_h<6><<<dim3(4, 64), 256, GH_SMEM>>>(pctxh, pwt + WT_OUT + (size_t)l * 262144,
                                                 outB + l * DD, nullptr, px,
                                                 ptmph, nullptr, 512, 512);
        ln_h<0><<<ROWS, 128>>>(ptmph, ln1s + l * DD, ln1b + l * DD, px, pxh);
        gemm_h<1><<<dim3(16, 64), 256, GH_SMEM>>>(pxh, pwt + WT_FF1 + (size_t)l * 1048576,
                                                  ff1B + l * FF_, nullptr, nullptr,
                                                  pffh, nullptr, 2048, 512);
        // tmph = ff @ ff2W + ff2B + x(f32)
        gemm_h<6><<<dim3(4, 64), 256, GH_SMEM>>>(pffh, pwt + WT_FF2 + (size_t)l * 1048576,
                                                 ff2B + l * DD, nullptr, px,
                                                 ptmph, nullptr, 512, 2048);
        if (l == LL - 1)
            ln_h<1><<<ROWS, 128>>>(ptmph, ln2s + l * DD, ln2b + l * DD, emb, nullptr);
        else
            ln_h<0><<<ROWS, 128>>>(ptmph, ln2s + l * DD, ln2b + l * DD, px, pxh);
    }

    pool_partial<<<BB * 32, DD>>>(emb, ppp);
    pool_reduce<<<BB, DD>>>(ppp, ppool);
    small_linear<<<BB, 2 * LAT>>>(ppool, mu1W, mu1B, ph, DD, 2 * LAT, 1);
    small_linear<<<BB, LAT>>>(ph, mu2W, mu2B, mu, 2 * LAT, LAT, 0);
    small_linear<<<BB, 2 * LAT>>>(ppool, lv1W, lv1B, ph, DD, 2 * LAT, 1);
    small_linear<<<BB, LAT>>>(ph, lv2W, lv2B, lv, 2 * LAT, LAT, 0);
}

// round 16
// speedup vs baseline: 1.0447x; 1.0447x over previous
#include <cuda_runtime.h>
#include <cuda_fp16.h>
#include <math.h>
#include <stdint.h>

// Problem constants
#define BB 4
#define TT 2048
#define INF_ 64
#define DD 512
#define HH 8
#define DH 64
#define FF_ 2048
#define LL 4
#define LAT 128
#define PAST 40
#define FUT 120
#define ROWS (BB*TT)          // 8192
#define EPS 1e-5f

// ---------------- scratch (device globals; no allocation allowed) ----------
__device__ float   g_pool[BB * DD];
__device__ float   g_pp  [BB * 32 * DD];
__device__ __half  g_xh  [ROWS * DD];        // x (half, LN output)
__device__ __half  g_tmph[ROWS * DD];        // pre-LN sums (half)
__device__ __half  g_qkvh[ROWS * 3 * DD];    // qkv (half)
__device__ __half  g_ctxh[ROWS * DD];        // attention output (half)
__device__ __half  g_ffh [ROWS * FF_];       // ff1 output (half)
__device__ __half  g_fh  [ROWS * INF_];      // feats (half)
__device__ uint32_t g_wh [6307840];          // weights k-pair-packed half2

// word offsets into g_wh
#define WH_PROJ 0
#define WH_QKV  16384
#define WH_OUT  1589248
#define WH_FF1  2113536
#define WH_FF2  4210688
#define WH_TOT  6307840
#define FH_W    (ROWS * INF_ / 2)            // 262144 feats half2 words

// ---------------- helpers ---------------------------------------------------
__device__ __forceinline__ uint32_t pack_h2f(float lo, float hi) {
    __half2 h = __floats2half2_rn(lo, hi);
    return *reinterpret_cast<uint32_t*>(&h);
}
__device__ __forceinline__ uint32_t sptr(const void* p) {
    return (uint32_t)__cvta_generic_to_shared(p);
}
__device__ __forceinline__ void cpa16(uint32_t dst, const void* src) {
    asm volatile("cp.async.cg.shared.global [%0], [%1], 16;\n" :: "r"(dst), "l"(src));
}
#define CP_COMMIT() asm volatile("cp.async.commit_group;\n")
#define CP_WAIT(n)  asm volatile("cp.async.wait_group %0;\n" :: "n"(n))

#define MMA_F16(d0,d1,d2,d3,a0,a1,a2,a3,b0,b1)                               \
    asm volatile("mma.sync.aligned.m16n8k16.row.col.f32.f16.f16.f32 "        \
        "{%0,%1,%2,%3},{%4,%5,%6,%7},{%8,%9},{%0,%1,%2,%3};"                 \
        : "+f"(d0),"+f"(d1),"+f"(d2),"+f"(d3)                                \
        : "r"(a0),"r"(a1),"r"(a2),"r"(a3),"r"(b0),"r"(b1))

#define LDMATRIX_X4(r0,r1,r2,r3,addr)                                        \
    asm volatile("ldmatrix.sync.aligned.m8n8.x4.shared.b16 {%0,%1,%2,%3}, [%4];" \
        : "=r"(r0),"=r"(r1),"=r"(r2),"=r"(r3) : "r"(addr))

// ---------------- fused prep: feats conv + all weight k-pair packing --------
__global__ void prep_all(const float* __restrict__ feats,
                         const float* __restrict__ projW,
                         const float* __restrict__ qkvW,
                         const float* __restrict__ outW,
                         const float* __restrict__ ff1W,
                         const float* __restrict__ ff2W,
                         __half* __restrict__ fh, uint32_t* __restrict__ wh)
{
    long w = (long)blockIdx.x * 256 + threadIdx.x;
    if (w < FH_W) {
        const float2 v = ((const float2*)feats)[w];
        ((__half2*)fh)[w] = __floats2half2_rn(v.x, v.y);
        return;
    }
    w -= FH_W;
    if (w >= WH_TOT) return;
    const long dstw = w;
    const float* W; int K, N;
    if (w < WH_QKV) {
        W = projW; K = 64; N = 512;
    } else if (w < WH_OUT) {
        w -= WH_QKV;
        const int l = (int)(w / 393216); w -= (long)l * 393216;
        W = qkvW + (size_t)l * 512 * 1536; K = 512; N = 1536;
    } else if (w < WH_FF1) {
        w -= WH_OUT;
        const int l = (int)(w / 131072); w -= (long)l * 131072;
        W = outW + (size_t)l * 512 * 512; K = 512; N = 512;
    } else if (w < WH_FF2) {
        w -= WH_FF1;
        const int l = (int)(w / 524288); w -= (long)l * 524288;
        W = ff1W + (size_t)l * 512 * 2048; K = 512; N = 2048;
    } else {
        w -= WH_FF2;
        const int l = (int)(w / 524288); w -= (long)l * 524288;
        W = ff2W + (size_t)l * 2048 * 512; K = 2048; N = 512;
    }
    const int kp = (int)(w / N), n = (int)(w - (long)kp * N);
    wh[dstw] = pack_h2f(W[(size_t)(2 * kp) * N + n], W[(size_t)(2 * kp + 1) * N + n]);
    (void)K;
}

// ---------------- FP16 GEMM, cp.async 4-stage, ldmatrix A-frags -------------
// C[M,N] = A[M,K] @ B[K,N] + bias. BM=BN=128, BK=32, 8 warps.
// EPI: 1 = +bias, relu -> Ch ; 2 = +bias+posenc(f32) -> Ch ;
//      3 = +bias -> Ch ; 5 = +bias + residh(half) -> Ch
#define AP2 20
#define BP2 136
#define GH_ASZ (128 * AP2)
#define GH_BSZ (16 * BP2)
#define GH_SMEM (4 * (GH_ASZ + GH_BSZ) * 4)   // 75776 B

template <int EPI>
__global__ __launch_bounds__(256, 2)
void gemm_h(const __half* __restrict__ A, const uint32_t* __restrict__ Bp,
            const float* __restrict__ bias, const float* __restrict__ extraf,
            const __half* __restrict__ residh, __half* __restrict__ Ch,
            int N, int K)
{
    extern __shared__ uint32_t smw[];
    uint32_t* As = smw;                  // [4][128][20]
    uint32_t* Bs = smw + 4 * GH_ASZ;     // [4][16][136]

    const int tid  = threadIdx.x;
    const int wid  = tid >> 5, lane = tid & 31;
    const int g    = lane >> 2, c = lane & 3;
    const int wm   = (wid >> 2) * 64;
    const int wn   = (wid & 3) * 32;
    const int brow = blockIdx.y * 128, bcol = blockIdx.x * 128;

    const int arow = tid >> 1, ach = tid & 1;
    const int bkr = tid >> 4, bn0 = (tid & 15) * 8;

    const __half* Ag = A + (size_t)(brow + arow) * K + ach * 16;
    const uint32_t* Bg = Bp + bcol + bn0 + (size_t)bkr * N;

    const uint32_t sA = sptr(As) + (uint32_t)(arow * AP2 + ach * 8) * 4u;
    const uint32_t sB = sptr(Bs) + (uint32_t)(bkr * BP2 + bn0) * 4u;
    const uint32_t lmoff = (uint32_t)((lane & 15) * AP2 + (lane >> 4) * 4) * 4u;

    float acc[4][4][4];
#pragma unroll
    for (int i = 0; i < 4; i++)
#pragma unroll
        for (int j = 0; j < 4; j++)
#pragma unroll
            for (int r = 0; r < 4; r++) acc[i][j][r] = 0.f;

    const int nk = K >> 5;

    auto issue = [&](int i, int sl) {
        const __half* ga = Ag + (size_t)i * 32;
        cpa16(sA + sl * GH_ASZ * 4, ga);
        cpa16(sA + sl * GH_ASZ * 4 + 16, ga + 8);
        const uint32_t* gb = Bg + (size_t)i * 16 * N;
        cpa16(sB + sl * GH_BSZ * 4, gb);
        cpa16(sB + sl * GH_BSZ * 4 + 16, gb + 4);
        CP_COMMIT();
    };

    issue(0, 0);
    if (nk > 1) issue(1, 1);
    if (nk > 2) issue(2, 2);
    if (nk > 2)      CP_WAIT(2);
    else if (nk > 1) CP_WAIT(1);
    else             CP_WAIT(0);
    __syncthreads();

    for (int s = 0; s < nk; s++) {
        if (s + 3 < nk) issue(s + 3, (s + 3) & 3);

        const int sl = s & 3;
        const uint32_t aBase = sptr(As) + (uint32_t)(sl * GH_ASZ) * 4u + lmoff;
        const uint32_t* Bb = Bs + sl * GH_BSZ;
#pragma unroll
        for (int kk = 0; kk < 2; kk++) {
            uint32_t af[4][4];
#pragma unroll
            for (int mt = 0; mt < 4; mt++) {
                const uint32_t addr = aBase
                    + (uint32_t)(((wm + mt * 16) * AP2 + kk * 8) * 4);
                LDMATRIX_X4(af[mt][0], af[mt][1], af[mt][2], af[mt][3], addr);
            }
            uint32_t bf[4][2];
#pragma unroll
            for (int nt = 0; nt < 4; nt++) {
                const int n0 = wn + nt * 8 + g;
                bf[nt][0] = Bb[(kk * 8 + c    ) * BP2 + n0];
                bf[nt][1] = Bb[(kk * 8 + c + 4) * BP2 + n0];
            }
#pragma unroll
            for (int mt = 0; mt < 4; mt++)
#pragma unroll
                for (int nt = 0; nt < 4; nt++)
                    MMA_F16(acc[mt][nt][0], acc[mt][nt][1], acc[mt][nt][2], acc[mt][nt][3],
                            af[mt][0], af[mt][1], af[mt][2], af[mt][3],
                            bf[nt][0], bf[nt][1]);
        }

        if (s + 1 < nk) {
            if (s + 3 < nk)      CP_WAIT(2);
            else if (s + 2 < nk) CP_WAIT(1);
            else                 CP_WAIT(0);
            __syncthreads();
        }
    }

    // epilogue: frag (row g/g+8, col 2c/2c+1); all outputs half
#pragma unroll
    for (int mt = 0; mt < 4; mt++) {
#pragma unroll
        for (int nt = 0; nt < 4; nt++) {
            const int col = bcol + wn + nt * 8 + 2 * c;
            const float b0 = bias[col], b1 = bias[col + 1];
#pragma unroll
            for (int half = 0; half < 2; half++) {
                const int row = brow + wm + mt * 16 + g + half * 8;
                float v0 = acc[mt][nt][half * 2 + 0] + b0;
                float v1 = acc[mt][nt][half * 2 + 1] + b1;
                if (EPI == 1) {
                    v0 = fmaxf(v0, 0.f); v1 = fmaxf(v1, 0.f);
                } else if (EPI == 2) {
                    const int t = row & (TT - 1);
                    const float2 p = *(const float2*)(extraf + (size_t)t * N + col);
                    v0 += p.x; v1 += p.y;
                } else if (EPI == 5) {
                    const __half2 rh = *(const __half2*)(residh + (size_t)row * N + col);
                    const float2 rf = __half22float2(rh);
                    v0 += rf.x; v1 += rf.y;
                }
                *(__half2*)(Ch + (size_t)row * N + col) = __floats2half2_rn(v0, v1);
            }
        }
    }
}

// ---------------- banded flash attention, full fp16 --------------------------
#define KVPH 72
#define ABUFH (64 * KVPH)
#define ATTN_SMEM (4 * ABUFH * 2)    // 36864 B

__global__ __launch_bounds__(256, 2)
void attn_h(const __half* __restrict__ qkvh, __half* __restrict__ ctxh)
{
    extern __shared__ __half smh[];
    __half* Ks = smh;
    __half* Vs = smh + 2 * ABUFH;

    const int blk = blockIdx.x;
    const int qt = blk & 15;
    const int h  = (blk >> 4) & 7;
    const int b  = blk >> 7;
    const int q0 = qt * 128;

    const int tid = threadIdx.x, wid = tid >> 5, lane = tid & 31;
    const int g = lane >> 2, c = lane & 3;
    const int w0 = q0 + wid * 16;
    const int r0 = w0 + g, r1 = r0 + 8;

    uint32_t qa[4][4];
    {
        const uint32_t* qlo = (const uint32_t*)(qkvh + (size_t)(b * TT + r0) * 1536 + h * 64);
        const uint32_t* qhi = (const uint32_t*)(qkvh + (size_t)(b * TT + r1) * 1536 + h * 64);
#pragma unroll
        for (int kt = 0; kt < 4; kt++) {
            qa[kt][0] = qlo[kt * 8 + c];
            qa[kt][1] = qhi[kt * 8 + c];
            qa[kt][2] = qlo[kt * 8 + c + 4];
            qa[kt][3] = qhi[kt * 8 + c + 4];
        }
    }

    float oacc[8][4];
#pragma unroll
    for (int nt = 0; nt < 8; nt++)
#pragma unroll
        for (int e = 0; e < 4; e++) oacc[nt][e] = 0.f;

    float m0 = -INFINITY, m1 = -INFINITY, l0 = 0.f, l1 = 0.f;
    const float scale = 0.125f;

    int csv[5]; int ncs = 0;
    const int offs[5] = {-64, 0, 64, 128, 192};
#pragma unroll
    for (int i = 0; i < 5; i++) {
        const int cs = q0 + offs[i];
        if (cs >= 0 && cs < TT) csv[ncs++] = cs;
    }

    const int lrow  = (tid >> 1) & 63;
    const int isv   = tid >> 7;
    const int lhalf = tid & 1;
    const uint32_t ldst0 = sptr((isv ? Vs : Ks) + lrow * KVPH + lhalf * 32);
    const size_t lsrc_off = (size_t)512 + (size_t)isv * 512 + h * 64 + lhalf * 32;

    {
        const __half* src = qkvh + (size_t)(b * TT + csv[0] + lrow) * 1536 + lsrc_off;
#pragma unroll
        for (int i = 0; i < 4; i++) cpa16(ldst0 + i * 16, src + i * 8);
        CP_COMMIT();
    }

    for (int ci = 0; ci < ncs; ci++) {
        CP_WAIT(0);
        __syncthreads();

        if (ci + 1 < ncs) {
            const uint32_t dst = ldst0 + ((ci + 1) & 1) * ABUFH * 2;
            const __half* src = qkvh + (size_t)(b * TT + csv[ci + 1] + lrow) * 1536 + lsrc_off;
#pragma unroll
            for (int i = 0; i < 4; i++) cpa16(dst + i * 16, src + i * 8);
            CP_COMMIT();
        }

        const int cs = csv[ci];
        const int lo_key = max(cs, w0 - PAST);
        const int hi_key = min(cs + 63, w0 + 15 + FUT);
        if (lo_key > hi_key) continue;
        const int ntlo = (lo_key - cs) >> 3;
        const int nthi = (hi_key - cs) >> 3;

        const __half* Kb = Ks + (ci & 1) * ABUFH;
        const __half* Vb = Vs + (ci & 1) * ABUFH;

        float sacc[8][4];
#pragma unroll
        for (int nt = 0; nt < 8; nt++) {
            sacc[nt][0] = 0.f; sacc[nt][1] = 0.f;
            sacc[nt][2] = 0.f; sacc[nt][3] = 0.f;
        }
#pragma unroll
        for (int nt = 0; nt < 8; nt++) {
            if (nt < ntlo || nt > nthi) continue;
            const __half* krow = Kb + (nt * 8 + g) * KVPH;
#pragma unroll
            for (int kt = 0; kt < 4; kt++) {
                const uint32_t b0 = *(const uint32_t*)(krow + kt * 16 + 2 * c);
                const uint32_t b1 = *(const uint32_t*)(krow + kt * 16 + 2 * c + 8);
                MMA_F16(sacc[nt][0], sacc[nt][1], sacc[nt][2], sacc[nt][3],
                        qa[kt][0], qa[kt][1], qa[kt][2], qa[kt][3], b0, b1);
            }
        }

        float mx0 = -INFINITY, mx1 = -INFINITY;
#pragma unroll
        for (int nt = 0; nt < 8; nt++) {
            if (nt < ntlo || nt > nthi) continue;
            const int j0 = cs + nt * 8 + 2 * c;
            const int j1 = j0 + 1;
            float v;
            v = sacc[nt][0] * scale;
            v = (j0 >= r0 - PAST && j0 <= r0 + FUT) ? v : -INFINITY;
            sacc[nt][0] = v; mx0 = fmaxf(mx0, v);
            v = sacc[nt][1] * scale;
            v = (j1 >= r0 - PAST && j1 <= r0 + FUT) ? v : -INFINITY;
            sacc[nt][1] = v; mx0 = fmaxf(mx0, v);
            v = sacc[nt][2] * scale;
            v = (j0 >= r1 - PAST && j0 <= r1 + FUT) ? v : -INFINITY;
            sacc[nt][2] = v; mx1 = fmaxf(mx1, v);
            v = sacc[nt][3] * scale;
            v = (j1 >= r1 - PAST && j1 <= r1 + FUT) ? v : -INFINITY;
            sacc[nt][3] = v; mx1 = fmaxf(mx1, v);
        }
        mx0 = fmaxf(mx0, __shfl_xor_sync(0xffffffffu, mx0, 1));
        mx0 = fmaxf(mx0, __shfl_xor_sync(0xffffffffu, mx0, 2));
        mx1 = fmaxf(mx1, __shfl_xor_sync(0xffffffffu, mx1, 1));
        mx1 = fmaxf(mx1, __shfl_xor_sync(0xffffffffu, mx1, 2));

        const float mn0 = fmaxf(m0, mx0);
        const float mn1 = fmaxf(m1, mx1);
        const float rf0 = __expf(fmaxf(m0 - mn0, -88.f));
        const float rf1 = __expf(fmaxf(m1 - mn1, -88.f));
        m0 = mn0; m1 = mn1;

        float ps0 = 0.f, ps1 = 0.f;
#pragma unroll
        for (int nt = 0; nt < 8; nt++) {
            if (nt < ntlo || nt > nthi) continue;
            const float p00 = __expf(fmaxf(sacc[nt][0] - mn0, -88.f));
            const float p01 = __expf(fmaxf(sacc[nt][1] - mn0, -88.f));
            const float p10 = __expf(fmaxf(sacc[nt][2] - mn1, -88.f));
            const float p11 = __expf(fmaxf(sacc[nt][3] - mn1, -88.f));
            ps0 += p00 + p01;
            ps1 += p10 + p11;
            sacc[nt][0] = p00; sacc[nt][1] = p01;
            sacc[nt][2] = p10; sacc[nt][3] = p11;
        }
        ps0 += __shfl_xor_sync(0xffffffffu, ps0, 1);
        ps0 += __shfl_xor_sync(0xffffffffu, ps0, 2);
        ps1 += __shfl_xor_sync(0xffffffffu, ps1, 1);
        ps1 += __shfl_xor_sync(0xffffffffu, ps1, 2);
        l0 = l0 * rf0 + ps0;
        l1 = l1 * rf1 + ps1;

#pragma unroll
        for (int nt = 0; nt < 8; nt++) {
            oacc[nt][0] *= rf0; oacc[nt][1] *= rf0;
            oacc[nt][2] *= rf1; oacc[nt][3] *= rf1;
        }

#pragma unroll
        for (int kp = 0; kp < 4; kp++) {
            const int nt0 = 2 * kp, nt1 = 2 * kp + 1;
            if (nt1 < ntlo || nt0 > nthi) continue;
            const uint32_t a0 = pack_h2f(sacc[nt0][0], sacc[nt0][1]);
            const uint32_t a1 = pack_h2f(sacc[nt0][2], sacc[nt0][3]);
            const uint32_t a2 = pack_h2f(sacc[nt1][0], sacc[nt1][1]);
            const uint32_t a3 = pack_h2f(sacc[nt1][2], sacc[nt1][3]);
            const __half* v0r = Vb + (kp * 16 + 2 * c) * KVPH;
            const __half* v1r = v0r + KVPH;
            const __half* v8r = v0r + 8 * KVPH;
            const __half* v9r = v8r + KVPH;
#pragma unroll
            for (int nt = 0; nt < 8; nt++) {
                const int n = nt * 8 + g;
                const uint32_t b0 = *reinterpret_cast<const uint32_t*>(
                    &__halves2half2(v0r[n], v1r[n]));
                const uint32_t b1 = *reinterpret_cast<const uint32_t*>(
                    &__halves2half2(v8r[n], v9r[n]));
                MMA_F16(oacc[nt][0], oacc[nt][1], oacc[nt][2], oacc[nt][3],
                        a0, a1, a2, a3, b0, b1);
            }
        }
    }

    const float inv0 = 1.f / l0, inv1 = 1.f / l1;
#pragma unroll
    for (int nt = 0; nt < 8; nt++) {
        const int col = h * 64 + nt * 8 + 2 * c;
        *(__half2*)(ctxh + (size_t)(b * TT + r0) * DD + col) =
            __floats2half2_rn(oacc[nt][0] * inv0, oacc[nt][1] * inv0);
        *(__half2*)(ctxh + (size_t)(b * TT + r1) * DD + col) =
            __floats2half2_rn(oacc[nt][2] * inv1, oacc[nt][3] * inv1);
    }
}

// ---------------- LayerNorm on half input; half or f32 output ---------------
template <int OUTF>
__global__ __launch_bounds__(128)
void ln_h(const __half* __restrict__ xin,
          const float* __restrict__ s, const float* __restrict__ bta,
          float* __restrict__ outf, __half* __restrict__ outh)
{
    const int row = blockIdx.x;
    const int tid = threadIdx.x;
    const __half2* xrow = (const __half2*)(xin + (size_t)row * DD);
    float2 v[2];
    float sum = 0.f, sq = 0.f;
#pragma unroll
    for (int i = 0; i < 2; i++) {
        const float2 f = __half22float2(xrow[tid + i * 128]);
        v[i] = f;
        sum += f.x + f.y;
        sq  += f.x * f.x + f.y * f.y;
    }
    __shared__ float rs[8];
#pragma unroll
    for (int off = 16; off > 0; off >>= 1) {
        sum += __shfl_xor_sync(0xffffffffu, sum, off);
        sq  += __shfl_xor_sync(0xffffffffu, sq,  off);
    }
    if ((tid & 31) == 0) { rs[tid >> 5] = sum; rs[4 + (tid >> 5)] = sq; }
    __syncthreads();
    sum = rs[0] + rs[1] + rs[2] + rs[3];
    sq  = rs[4] + rs[5] + rs[6] + rs[7];
    const float mean = sum * (1.f / DD);
    const float var  = sq * (1.f / DD) - mean * mean;
    const float inv  = rsqrtf(var + EPS);
#pragma unroll
    for (int i = 0; i < 2; i++) {
        const int cw = tid + i * 128;
        const int c0 = 2 * cw;
        const float o0 = (v[i].x - mean) * inv * s[c0]     + bta[c0];
        const float o1 = (v[i].y - mean) * inv * s[c0 + 1] + bta[c0 + 1];
        if (OUTF) {
            float2 o; o.x = o0; o.y = o1;
            *(float2*)(outf + (size_t)row * DD + c0) = o;
        } else {
            ((__half2*)(outh + (size_t)row * DD))[cw] = __floats2half2_rn(o0, o1);
        }
    }
}

// ---------------- mean pool partial ------------------------------------------
__global__ void pool_partial(const float* __restrict__ emb, float* __restrict__ pp)
{
    const int b = blockIdx.x >> 5, ch = blockIdx.x & 31;
    const int d = threadIdx.x;
    float s = 0.f;
    const int t0 = ch * 64;
    for (int t = t0; t < t0 + 64; t++)
        s += emb[((size_t)(b * TT + t)) * DD + d];
    pp[(size_t)blockIdx.x * DD + d] = s;
}

// ---------------- fused heads: pool-reduce + mu path + lv path --------------
__global__ __launch_bounds__(256)
void heads(const float* __restrict__ pp,
           const float* __restrict__ mu1W, const float* __restrict__ mu1B,
           const float* __restrict__ mu2W, const float* __restrict__ mu2B,
           const float* __restrict__ lv1W, const float* __restrict__ lv1B,
           const float* __restrict__ lv2W, const float* __restrict__ lv2B,
           float* __restrict__ mu, float* __restrict__ lv)
{
    const int b = blockIdx.x, tid = threadIdx.x;
    __shared__ float p[DD];
    __shared__ float hb[2 * LAT];

    for (int d = tid; d < DD; d += 256) {
        float s = 0.f;
        for (int ch = 0; ch < 32; ch++)
            s += pp[(size_t)(b * 32 + ch) * DD + d];
        p[d] = s * (1.f / TT);
    }
    __syncthreads();

    // mu hidden: 256 outputs
    {
        float s = mu1B[tid];
        for (int k = 0; k < DD; k++)
            s = fmaf(p[k], mu1W[(size_t)k * 256 + tid], s);
        hb[tid] = fmaxf(s, 0.f);
    }
    __syncthreads();
    if (tid < LAT) {
        float s = mu2B[tid];
        for (int k = 0; k < 2 * LAT; k++)
            s = fmaf(hb[k], mu2W[(size_t)k * LAT + tid], s);
        mu[b * LAT + tid] = s;
    }
    __syncthreads();

    // lv hidden
    {
        float s = lv1B[tid];
        for (int k = 0; k < DD; k++)
            s = fmaf(p[k], lv1W[(size_t)k * 256 + tid], s);
        hb[tid] = fmaxf(s, 0.f);
    }
    __syncthreads();
    if (tid < LAT) {
        float s = lv2B[tid];
        for (int k = 0; k < 2 * LAT; k++)
            s = fmaf(hb[k], lv2W[(size_t)k * LAT + tid], s);
        lv[b * LAT + tid] = s;
    }
}

// ---------------- launch -----------------------------------------------------
extern "C" void kernel_launch(void* const* d_in, const int* in_sizes, int n_in,
                              void* d_out, int out_size)
{
    const float* feats  = (const float*)d_in[0];
    const float* projW  = (const float*)d_in[1];
    const float* projB  = (const float*)d_in[2];
    const float* posenc = (const float*)d_in[3];
    const float* qkvW   = (const float*)d_in[4];
    const float* qkvB   = (const float*)d_in[5];
    const float* outW   = (const float*)d_in[6];
    const float* outB   = (const float*)d_in[7];
    const float* ln1s   = (const float*)d_in[8];
    const float* ln1b   = (const float*)d_in[9];
    const float* ff1W   = (const float*)d_in[10];
    const float* ff1B   = (const float*)d_in[11];
    const float* ff2W   = (const float*)d_in[12];
    const float* ff2B   = (const float*)d_in[13];
    const float* ln2s   = (const float*)d_in[14];
    const float* ln2b   = (const float*)d_in[15];
    const float* mu1W   = (const float*)d_in[16];
    const float* mu1B   = (const float*)d_in[17];
    const float* mu2W   = (const float*)d_in[18];
    const float* mu2B   = (const float*)d_in[19];
    const float* lv1W   = (const float*)d_in[20];
    const float* lv1B   = (const float*)d_in[21];
    const float* lv2W   = (const float*)d_in[22];
    const float* lv2B   = (const float*)d_in[23];

    float *ppool, *ppp;
    __half *pxh, *ptmph, *pqkvh, *pctxh, *pffh, *pfh;
    uint32_t* pwh;
    cudaGetSymbolAddress((void**)&ppool, g_pool);
    cudaGetSymbolAddress((void**)&ppp,   g_pp);
    cudaGetSymbolAddress((void**)&pxh,   g_xh);
    cudaGetSymbolAddress((void**)&ptmph, g_tmph);
    cudaGetSymbolAddress((void**)&pqkvh, g_qkvh);
    cudaGetSymbolAddress((void**)&pctxh, g_ctxh);
    cudaGetSymbolAddress((void**)&pffh,  g_ffh);
    cudaGetSymbolAddress((void**)&pfh,   g_fh);
    cudaGetSymbolAddress((void**)&pwh,   g_wh);

    cudaFuncSetAttribute(gemm_h<1>, cudaFuncAttributeMaxDynamicSharedMemorySize, GH_SMEM);
    cudaFuncSetAttribute(gemm_h<2>, cudaFuncAttributeMaxDynamicSharedMemorySize, GH_SMEM);
    cudaFuncSetAttribute(gemm_h<3>, cudaFuncAttributeMaxDynamicSharedMemorySize, GH_SMEM);
    cudaFuncSetAttribute(gemm_h<5>, cudaFuncAttributeMaxDynamicSharedMemorySize, GH_SMEM);
    cudaFuncSetAttribute(attn_h,    cudaFuncAttributeMaxDynamicSharedMemorySize, ATTN_SMEM);

    float* emb = (float*)d_out;
    float* mu  = emb + (size_t)ROWS * DD;
    float* lv  = mu + BB * LAT;

    // fused prep: feats conv + all weight packing (1 launch)
    {
        const long total = FH_W + WH_TOT;
        prep_all<<<(unsigned)((total + 255) / 256), 256>>>(feats, projW, qkvW, outW,
                                                           ff1W, ff2W, pfh, pwh);
    }

    // x = feats @ projW + projB + posenc  (half)
    gemm_h<2><<<dim3(4, 64), 256, GH_SMEM>>>(pfh, pwh + WH_PROJ, projB, posenc,
                                             nullptr, pxh, 512, 64);

    for (int l = 0; l < LL; l++) {
        gemm_h<3><<<dim3(12, 64), 256, GH_SMEM>>>(pxh, pwh + WH_QKV + (size_t)l * 393216,
                                                  qkvB + l * 3 * DD, nullptr, nullptr,
                                                  pqkvh, 1536, 512);
        attn_h<<<BB * HH * 16, 256, ATTN_SMEM>>>(pqkvh, pctxh);
        gemm_h<5><<<dim3(4, 64), 256, GH_SMEM>>>(pctxh, pwh + WH_OUT + (size_t)l * 131072,
                                                 outB + l * DD, nullptr, pxh,
                                                 ptmph, 512, 512);
        ln_h<0><<<ROWS, 128>>>(ptmph, ln1s + l * DD, ln1b + l * DD, nullptr, pxh);
        gemm_h<1><<<dim3(16, 64), 256, GH_SMEM>>>(pxh, pwh + WH_FF1 + (size_t)l * 524288,
                                                  ff1B + l * FF_, nullptr, nullptr,
                                                  pffh, 2048, 512);
        gemm_h<5><<<dim3(4, 64), 256, GH_SMEM>>>(pffh, pwh + WH_FF2 + (size_t)l * 524288,
                                                 ff2B + l * DD, nullptr, pxh,
                                                 ptmph, 512, 2048);
        if (l == LL - 1)
            ln_h<1><<<ROWS, 128>>>(ptmph, ln2s + l * DD, ln2b + l * DD, emb, nullptr);
        else
            ln_h<0><<<ROWS, 128>>>(ptmph, ln2s + l * DD, ln2b + l * DD, nullptr, pxh);
    }

    pool_partial<<<BB * 32, DD>>>(emb, ppp);
    heads<<<BB, 256>>>(ppp, mu1W, mu1B, mu2W, mu2B, lv1W, lv1B, lv2W, lv2B, mu, lv);
}

// round 17
// speedup vs baseline: 1.0532x; 1.0081x over previous
#include <cuda_runtime.h>
#include <cuda_fp16.h>
#include <math.h>
#include <stdint.h>

// Problem constants
#define BB 4
#define TT 2048
#define INF_ 64
#define DD 512
#define HH 8
#define DH 64
#define FF_ 2048
#define LL 4
#define LAT 128
#define PAST 40
#define FUT 120
#define ROWS (BB*TT)          // 8192
#define EPS 1e-5f

// ---------------- scratch (device globals; no allocation allowed) ----------
__device__ float   g_pool[BB * DD];
__device__ float   g_pp  [BB * 32 * DD];
__device__ __half  g_xh  [ROWS * DD];        // x (half, LN output)
__device__ __half  g_tmph[ROWS * DD];        // pre-LN sums (half)
__device__ __half  g_qkvh[ROWS * 3 * DD];    // qkv (half)
__device__ __half  g_ctxh[ROWS * DD];        // attention output (half)
__device__ __half  g_ffh [ROWS * FF_];       // ff1 output (half)
__device__ __half  g_fh  [ROWS * INF_];      // feats (half)
__device__ uint32_t g_wh [6307840];          // weights k-pair-packed half2

// word offsets into g_wh
#define WH_PROJ 0
#define WH_QKV  16384
#define WH_OUT  1589248
#define WH_FF1  2113536
#define WH_FF2  4210688
#define WH_TOT  6307840
#define FH_W    (ROWS * INF_ / 2)            // 262144 feats half2 words

// ---------------- helpers ---------------------------------------------------
__device__ __forceinline__ uint32_t pack_h2f(float lo, float hi) {
    __half2 h = __floats2half2_rn(lo, hi);
    return *reinterpret_cast<uint32_t*>(&h);
}
__device__ __forceinline__ uint32_t sptr(const void* p) {
    return (uint32_t)__cvta_generic_to_shared(p);
}
__device__ __forceinline__ void cpa16(uint32_t dst, const void* src) {
    asm volatile("cp.async.cg.shared.global [%0], [%1], 16;\n" :: "r"(dst), "l"(src));
}
#define CP_COMMIT() asm volatile("cp.async.commit_group;\n")
#define CP_WAIT(n)  asm volatile("cp.async.wait_group %0;\n" :: "n"(n))

#define MMA_F16(d0,d1,d2,d3,a0,a1,a2,a3,b0,b1)                               \
    asm volatile("mma.sync.aligned.m16n8k16.row.col.f32.f16.f16.f32 "        \
        "{%0,%1,%2,%3},{%4,%5,%6,%7},{%8,%9},{%0,%1,%2,%3};"                 \
        : "+f"(d0),"+f"(d1),"+f"(d2),"+f"(d3)                                \
        : "r"(a0),"r"(a1),"r"(a2),"r"(a3),"r"(b0),"r"(b1))

#define LDMATRIX_X4(r0,r1,r2,r3,addr)                                        \
    asm volatile("ldmatrix.sync.aligned.m8n8.x4.shared.b16 {%0,%1,%2,%3}, [%4];" \
        : "=r"(r0),"=r"(r1),"=r"(r2),"=r"(r3) : "r"(addr))

// ---------------- fused prep: feats conv + all weight k-pair packing --------
__global__ void prep_all(const float* __restrict__ feats,
                         const float* __restrict__ projW,
                         const float* __restrict__ qkvW,
                         const float* __restrict__ outW,
                         const float* __restrict__ ff1W,
                         const float* __restrict__ ff2W,
                         __half* __restrict__ fh, uint32_t* __restrict__ wh)
{
    long w = (long)blockIdx.x * 256 + threadIdx.x;
    if (w < FH_W) {
        const float2 v = ((const float2*)feats)[w];
        ((__half2*)fh)[w] = __floats2half2_rn(v.x, v.y);
        return;
    }
    w -= FH_W;
    if (w >= WH_TOT) return;
    const long dstw = w;
    const float* W; int N;
    if (w < WH_QKV) {
        W = projW; N = 512;
    } else if (w < WH_OUT) {
        w -= WH_QKV;
        const int l = (int)(w / 393216); w -= (long)l * 393216;
        W = qkvW + (size_t)l * 512 * 1536; N = 1536;
    } else if (w < WH_FF1) {
        w -= WH_OUT;
        const int l = (int)(w / 131072); w -= (long)l * 131072;
        W = outW + (size_t)l * 512 * 512; N = 512;
    } else if (w < WH_FF2) {
        w -= WH_FF1;
        const int l = (int)(w / 524288); w -= (long)l * 524288;
        W = ff1W + (size_t)l * 512 * 2048; N = 2048;
    } else {
        w -= WH_FF2;
        const int l = (int)(w / 524288); w -= (long)l * 524288;
        W = ff2W + (size_t)l * 2048 * 512; N = 512;
    }
    const int kp = (int)(w / N), n = (int)(w - (long)kp * N);
    wh[dstw] = pack_h2f(W[(size_t)(2 * kp) * N + n], W[(size_t)(2 * kp + 1) * N + n]);
}

// ---------------- FP16 GEMM, cp.async 4-stage, ldmatrix A-frags -------------
// C[M,N] = A[M,K] @ B[K,N] + bias. BM=BN=128, BK=32, 8 warps.
// EPI: 1 = +bias, relu -> Ch ; 2 = +bias+posenc(f32) -> Ch ;
//      3 = +bias -> Ch ; 5 = +bias + residh(half) -> Ch
#define AP2 20
#define BP2 136
#define GH_ASZ (128 * AP2)
#define GH_BSZ (16 * BP2)
#define GH_SMEM (4 * (GH_ASZ + GH_BSZ) * 4)   // 75776 B

template <int EPI>
__global__ __launch_bounds__(256, 2)
void gemm_h(const __half* __restrict__ A, const uint32_t* __restrict__ Bp,
            const float* __restrict__ bias, const float* __restrict__ extraf,
            const __half* __restrict__ residh, __half* __restrict__ Ch,
            int N, int K)
{
    extern __shared__ uint32_t smw[];
    uint32_t* As = smw;                  // [4][128][20]
    uint32_t* Bs = smw + 4 * GH_ASZ;     // [4][16][136]

    const int tid  = threadIdx.x;
    const int wid  = tid >> 5, lane = tid & 31;
    const int g    = lane >> 2, c = lane & 3;
    const int wm   = (wid >> 2) * 64;
    const int wn   = (wid & 3) * 32;
    const int brow = blockIdx.y * 128, bcol = blockIdx.x * 128;

    const int arow = tid >> 1, ach = tid & 1;
    const int bkr = tid >> 4, bn0 = (tid & 15) * 8;

    const __half* Ag = A + (size_t)(brow + arow) * K + ach * 16;
    const uint32_t* Bg = Bp + bcol + bn0 + (size_t)bkr * N;

    const uint32_t sA = sptr(As) + (uint32_t)(arow * AP2 + ach * 8) * 4u;
    const uint32_t sB = sptr(Bs) + (uint32_t)(bkr * BP2 + bn0) * 4u;
    const uint32_t lmoff = (uint32_t)((lane & 15) * AP2 + (lane >> 4) * 4) * 4u;

    float acc[4][4][4];
#pragma unroll
    for (int i = 0; i < 4; i++)
#pragma unroll
        for (int j = 0; j < 4; j++)
#pragma unroll
            for (int r = 0; r < 4; r++) acc[i][j][r] = 0.f;

    const int nk = K >> 5;

    auto issue = [&](int i, int sl) {
        const __half* ga = Ag + (size_t)i * 32;
        cpa16(sA + sl * GH_ASZ * 4, ga);
        cpa16(sA + sl * GH_ASZ * 4 + 16, ga + 8);
        const uint32_t* gb = Bg + (size_t)i * 16 * N;
        cpa16(sB + sl * GH_BSZ * 4, gb);
        cpa16(sB + sl * GH_BSZ * 4 + 16, gb + 4);
        CP_COMMIT();
    };

    issue(0, 0);
    if (nk > 1) issue(1, 1);
    if (nk > 2) issue(2, 2);
    if (nk > 2)      CP_WAIT(2);
    else if (nk > 1) CP_WAIT(1);
    else             CP_WAIT(0);
    __syncthreads();

    for (int s = 0; s < nk; s++) {
        if (s + 3 < nk) issue(s + 3, (s + 3) & 3);

        const int sl = s & 3;
        const uint32_t aBase = sptr(As) + (uint32_t)(sl * GH_ASZ) * 4u + lmoff;
        const uint32_t* Bb = Bs + sl * GH_BSZ;
#pragma unroll
        for (int kk = 0; kk < 2; kk++) {
            uint32_t af[4][4];
#pragma unroll
            for (int mt = 0; mt < 4; mt++) {
                const uint32_t addr = aBase
                    + (uint32_t)(((wm + mt * 16) * AP2 + kk * 8) * 4);
                LDMATRIX_X4(af[mt][0], af[mt][1], af[mt][2], af[mt][3], addr);
            }
            uint32_t bf[4][2];
#pragma unroll
            for (int nt = 0; nt < 4; nt++) {
                const int n0 = wn + nt * 8 + g;
                bf[nt][0] = Bb[(kk * 8 + c    ) * BP2 + n0];
                bf[nt][1] = Bb[(kk * 8 + c + 4) * BP2 + n0];
            }
#pragma unroll
            for (int mt = 0; mt < 4; mt++)
#pragma unroll
                for (int nt = 0; nt < 4; nt++)
                    MMA_F16(acc[mt][nt][0], acc[mt][nt][1], acc[mt][nt][2], acc[mt][nt][3],
                            af[mt][0], af[mt][1], af[mt][2], af[mt][3],
                            bf[nt][0], bf[nt][1]);
        }

        if (s + 1 < nk) {
            if (s + 3 < nk)      CP_WAIT(2);
            else if (s + 2 < nk) CP_WAIT(1);
            else                 CP_WAIT(0);
            __syncthreads();
        }
    }

    // epilogue: frag (row g/g+8, col 2c/2c+1); all outputs half
#pragma unroll
    for (int mt = 0; mt < 4; mt++) {
#pragma unroll
        for (int nt = 0; nt < 4; nt++) {
            const int col = bcol + wn + nt * 8 + 2 * c;
            const float b0 = bias[col], b1 = bias[col + 1];
#pragma unroll
            for (int half = 0; half < 2; half++) {
                const int row = brow + wm + mt * 16 + g + half * 8;
                float v0 = acc[mt][nt][half * 2 + 0] + b0;
                float v1 = acc[mt][nt][half * 2 + 1] + b1;
                if (EPI == 1) {
                    v0 = fmaxf(v0, 0.f); v1 = fmaxf(v1, 0.f);
                } else if (EPI == 2) {
                    const int t = row & (TT - 1);
                    const float2 p = *(const float2*)(extraf + (size_t)t * N + col);
                    v0 += p.x; v1 += p.y;
                } else if (EPI == 5) {
                    const __half2 rh = *(const __half2*)(residh + (size_t)row * N + col);
                    const float2 rf = __half22float2(rh);
                    v0 += rf.x; v1 += rf.y;
                }
                *(__half2*)(Ch + (size_t)row * N + col) = __floats2half2_rn(v0, v1);
            }
        }
    }
}

// ---------------- banded flash attention, full fp16 --------------------------
#define KVPH 72
#define ABUFH (64 * KVPH)
#define ATTN_SMEM (4 * ABUFH * 2)    // 36864 B

__global__ __launch_bounds__(256, 2)
void attn_h(const __half* __restrict__ qkvh, __half* __restrict__ ctxh)
{
    extern __shared__ __half smh[];
    __half* Ks = smh;
    __half* Vs = smh + 2 * ABUFH;

    const int blk = blockIdx.x;
    const int qt = blk & 15;
    const int h  = (blk >> 4) & 7;
    const int b  = blk >> 7;
    const int q0 = qt * 128;

    const int tid = threadIdx.x, wid = tid >> 5, lane = tid & 31;
    const int g = lane >> 2, c = lane & 3;
    const int w0 = q0 + wid * 16;
    const int r0 = w0 + g, r1 = r0 + 8;

    uint32_t qa[4][4];
    {
        const uint32_t* qlo = (const uint32_t*)(qkvh + (size_t)(b * TT + r0) * 1536 + h * 64);
        const uint32_t* qhi = (const uint32_t*)(qkvh + (size_t)(b * TT + r1) * 1536 + h * 64);
#pragma unroll
        for (int kt = 0; kt < 4; kt++) {
            qa[kt][0] = qlo[kt * 8 + c];
            qa[kt][1] = qhi[kt * 8 + c];
            qa[kt][2] = qlo[kt * 8 + c + 4];
            qa[kt][3] = qhi[kt * 8 + c + 4];
        }
    }

    float oacc[8][4];
#pragma unroll
    for (int nt = 0; nt < 8; nt++)
#pragma unroll
        for (int e = 0; e < 4; e++) oacc[nt][e] = 0.f;

    float m0 = -INFINITY, m1 = -INFINITY, l0 = 0.f, l1 = 0.f;
    const float scale = 0.125f;

    int csv[5]; int ncs = 0;
    const int offs[5] = {-64, 0, 64, 128, 192};
#pragma unroll
    for (int i = 0; i < 5; i++) {
        const int cs = q0 + offs[i];
        if (cs >= 0 && cs < TT) csv[ncs++] = cs;
    }

    const int lrow  = (tid >> 1) & 63;
    const int isv   = tid >> 7;
    const int lhalf = tid & 1;
    const uint32_t ldst0 = sptr((isv ? Vs : Ks) + lrow * KVPH + lhalf * 32);
    const size_t lsrc_off = (size_t)512 + (size_t)isv * 512 + h * 64 + lhalf * 32;

    {
        const __half* src = qkvh + (size_t)(b * TT + csv[0] + lrow) * 1536 + lsrc_off;
#pragma unroll
        for (int i = 0; i < 4; i++) cpa16(ldst0 + i * 16, src + i * 8);
        CP_COMMIT();
    }

    for (int ci = 0; ci < ncs; ci++) {
        CP_WAIT(0);
        __syncthreads();

        if (ci + 1 < ncs) {
            const uint32_t dst = ldst0 + ((ci + 1) & 1) * ABUFH * 2;
            const __half* src = qkvh + (size_t)(b * TT + csv[ci + 1] + lrow) * 1536 + lsrc_off;
#pragma unroll
            for (int i = 0; i < 4; i++) cpa16(dst + i * 16, src + i * 8);
            CP_COMMIT();
        }

        const int cs = csv[ci];
        const int lo_key = max(cs, w0 - PAST);
        const int hi_key = min(cs + 63, w0 + 15 + FUT);
        if (lo_key > hi_key) continue;
        const int ntlo = (lo_key - cs) >> 3;
        const int nthi = (hi_key - cs) >> 3;

        const __half* Kb = Ks + (ci & 1) * ABUFH;
        const __half* Vb = Vs + (ci & 1) * ABUFH;

        float sacc[8][4];
#pragma unroll
        for (int nt = 0; nt < 8; nt++) {
            sacc[nt][0] = 0.f; sacc[nt][1] = 0.f;
            sacc[nt][2] = 0.f; sacc[nt][3] = 0.f;
        }
#pragma unroll
        for (int nt = 0; nt < 8; nt++) {
            if (nt < ntlo || nt > nthi) continue;
            const __half* krow = Kb + (nt * 8 + g) * KVPH;
#pragma unroll
            for (int kt = 0; kt < 4; kt++) {
                const uint32_t b0 = *(const uint32_t*)(krow + kt * 16 + 2 * c);
                const uint32_t b1 = *(const uint32_t*)(krow + kt * 16 + 2 * c + 8);
                MMA_F16(sacc[nt][0], sacc[nt][1], sacc[nt][2], sacc[nt][3],
                        qa[kt][0], qa[kt][1], qa[kt][2], qa[kt][3], b0, b1);
            }
        }

        float mx0 = -INFINITY, mx1 = -INFINITY;
#pragma unroll
        for (int nt = 0; nt < 8; nt++) {
            if (nt < ntlo || nt > nthi) continue;
            const int j0 = cs + nt * 8 + 2 * c;
            const int j1 = j0 + 1;
            float v;
            v = sacc[nt][0] * scale;
            v = (j0 >= r0 - PAST && j0 <= r0 + FUT) ? v : -INFINITY;
            sacc[nt][0] = v; mx0 = fmaxf(mx0, v);
            v = sacc[nt][1] * scale;
            v = (j1 >= r0 - PAST && j1 <= r0 + FUT) ? v : -INFINITY;
            sacc[nt][1] = v; mx0 = fmaxf(mx0, v);
            v = sacc[nt][2] * scale;
            v = (j0 >= r1 - PAST && j0 <= r1 + FUT) ? v : -INFINITY;
            sacc[nt][2] = v; mx1 = fmaxf(mx1, v);
            v = sacc[nt][3] * scale;
            v = (j1 >= r1 - PAST && j1 <= r1 + FUT) ? v : -INFINITY;
            sacc[nt][3] = v; mx1 = fmaxf(mx1, v);
        }
        mx0 = fmaxf(mx0, __shfl_xor_sync(0xffffffffu, mx0, 1));
        mx0 = fmaxf(mx0, __shfl_xor_sync(0xffffffffu, mx0, 2));
        mx1 = fmaxf(mx1, __shfl_xor_sync(0xffffffffu, mx1, 1));
        mx1 = fmaxf(mx1, __shfl_xor_sync(0xffffffffu, mx1, 2));

        const float mn0 = fmaxf(m0, mx0);
        const float mn1 = fmaxf(m1, mx1);
        const float rf0 = __expf(fmaxf(m0 - mn0, -88.f));
        const float rf1 = __expf(fmaxf(m1 - mn1, -88.f));
        m0 = mn0; m1 = mn1;

        float ps0 = 0.f, ps1 = 0.f;
#pragma unroll
        for (int nt = 0; nt < 8; nt++) {
            if (nt < ntlo || nt > nthi) continue;
            const float p00 = __expf(fmaxf(sacc[nt][0] - mn0, -88.f));
            const float p01 = __expf(fmaxf(sacc[nt][1] - mn0, -88.f));
            const float p10 = __expf(fmaxf(sacc[nt][2] - mn1, -88.f));
            const float p11 = __expf(fmaxf(sacc[nt][3] - mn1, -88.f));
            ps0 += p00 + p01;
            ps1 += p10 + p11;
            sacc[nt][0] = p00; sacc[nt][1] = p01;
            sacc[nt][2] = p10; sacc[nt][3] = p11;
        }
        ps0 += __shfl_xor_sync(0xffffffffu, ps0, 1);
        ps0 += __shfl_xor_sync(0xffffffffu, ps0, 2);
        ps1 += __shfl_xor_sync(0xffffffffu, ps1, 1);
        ps1 += __shfl_xor_sync(0xffffffffu, ps1, 2);
        l0 = l0 * rf0 + ps0;
        l1 = l1 * rf1 + ps1;

#pragma unroll
        for (int nt = 0; nt < 8; nt++) {
            oacc[nt][0] *= rf0; oacc[nt][1] *= rf0;
            oacc[nt][2] *= rf1; oacc[nt][3] *= rf1;
        }

#pragma unroll
        for (int kp = 0; kp < 4; kp++) {
            const int nt0 = 2 * kp, nt1 = 2 * kp + 1;
            if (nt1 < ntlo || nt0 > nthi) continue;
            const uint32_t a0 = pack_h2f(sacc[nt0][0], sacc[nt0][1]);
            const uint32_t a1 = pack_h2f(sacc[nt0][2], sacc[nt0][3]);
            const uint32_t a2 = pack_h2f(sacc[nt1][0], sacc[nt1][1]);
            const uint32_t a3 = pack_h2f(sacc[nt1][2], sacc[nt1][3]);
            const __half* v0r = Vb + (kp * 16 + 2 * c) * KVPH;
            const __half* v1r = v0r + KVPH;
            const __half* v8r = v0r + 8 * KVPH;
            const __half* v9r = v8r + KVPH;
#pragma unroll
            for (int nt = 0; nt < 8; nt++) {
                const int n = nt * 8 + g;
                const uint32_t b0 = *reinterpret_cast<const uint32_t*>(
                    &__halves2half2(v0r[n], v1r[n]));
                const uint32_t b1 = *reinterpret_cast<const uint32_t*>(
                    &__halves2half2(v8r[n], v9r[n]));
                MMA_F16(oacc[nt][0], oacc[nt][1], oacc[nt][2], oacc[nt][3],
                        a0, a1, a2, a3, b0, b1);
            }
        }
    }

    const float inv0 = 1.f / l0, inv1 = 1.f / l1;
#pragma unroll
    for (int nt = 0; nt < 8; nt++) {
        const int col = h * 64 + nt * 8 + 2 * c;
        *(__half2*)(ctxh + (size_t)(b * TT + r0) * DD + col) =
            __floats2half2_rn(oacc[nt][0] * inv0, oacc[nt][1] * inv0);
        *(__half2*)(ctxh + (size_t)(b * TT + r1) * DD + col) =
            __floats2half2_rn(oacc[nt][2] * inv1, oacc[nt][3] * inv1);
    }
}

// ---------------- warp-per-row LayerNorm on half input ----------------------
// 256 threads = 8 warps, each warp owns one row. No smem, no block barrier.
// OUTF = 0: write half to outh ; OUTF = 1: write f32 to outf
template <int OUTF>
__global__ __launch_bounds__(256)
void ln_h(const __half* __restrict__ xin,
          const float* __restrict__ s, const float* __restrict__ bta,
          float* __restrict__ outf, __half* __restrict__ outh)
{
    const int row  = blockIdx.x * 8 + (threadIdx.x >> 5);
    const int lane = threadIdx.x & 31;
    const __half2* xrow = (const __half2*)(xin + (size_t)row * DD);

    float2 v[8];
    float sum = 0.f, sq = 0.f;
#pragma unroll
    for (int i = 0; i < 8; i++) {
        const float2 f = __half22float2(xrow[lane + i * 32]);
        v[i] = f;
        sum += f.x + f.y;
        sq  += f.x * f.x + f.y * f.y;
    }
#pragma unroll
    for (int off = 16; off > 0; off >>= 1) {
        sum += __shfl_xor_sync(0xffffffffu, sum, off);
        sq  += __shfl_xor_sync(0xffffffffu, sq,  off);
    }
    const float mean = sum * (1.f / DD);
    const float var  = sq * (1.f / DD) - mean * mean;
    const float inv  = rsqrtf(var + EPS);
#pragma unroll
    for (int i = 0; i < 8; i++) {
        const int cw = lane + i * 32;
        const int c0 = 2 * cw;
        const float o0 = (v[i].x - mean) * inv * s[c0]     + bta[c0];
        const float o1 = (v[i].y - mean) * inv * s[c0 + 1] + bta[c0 + 1];
        if (OUTF) {
            float2 o; o.x = o0; o.y = o1;
            *(float2*)(outf + (size_t)row * DD + c0) = o;
        } else {
            ((__half2*)(outh + (size_t)row * DD))[cw] = __floats2half2_rn(o0, o1);
        }
    }
}

// ---------------- mean pool partial ------------------------------------------
__global__ void pool_partial(const float* __restrict__ emb, float* __restrict__ pp)
{
    const int b = blockIdx.x >> 5, ch = blockIdx.x & 31;
    const int d = threadIdx.x;
    float s = 0.f;
    const int t0 = ch * 64;
    for (int t = t0; t < t0 + 64; t++)
        s += emb[((size_t)(b * TT + t)) * DD + d];
    pp[(size_t)blockIdx.x * DD + d] = s;
}

// ---------------- fused heads: pool-reduce + mu path + lv path --------------
__global__ __launch_bounds__(256)
void heads(const float* __restrict__ pp,
           const float* __restrict__ mu1W, const float* __restrict__ mu1B,
           const float* __restrict__ mu2W, const float* __restrict__ mu2B,
           const float* __restrict__ lv1W, const float* __restrict__ lv1B,
           const float* __restrict__ lv2W, const float* __restrict__ lv2B,
           float* __restrict__ mu, float* __restrict__ lv)
{
    const int b = blockIdx.x, tid = threadIdx.x;
    __shared__ float p[DD];
    __shared__ float hb[2 * LAT];

    for (int d = tid; d < DD; d += 256) {
        float s = 0.f;
        for (int ch = 0; ch < 32; ch++)
            s += pp[(size_t)(b * 32 + ch) * DD + d];
        p[d] = s * (1.f / TT);
    }
    __syncthreads();

    {
        float s = mu1B[tid];
        for (int k = 0; k < DD; k++)
            s = fmaf(p[k], mu1W[(size_t)k * 256 + tid], s);
        hb[tid] = fmaxf(s, 0.f);
    }
    __syncthreads();
    if (tid < LAT) {
        float s = mu2B[tid];
        for (int k = 0; k < 2 * LAT; k++)
            s = fmaf(hb[k], mu2W[(size_t)k * LAT + tid], s);
        mu[b * LAT + tid] = s;
    }
    __syncthreads();

    {
        float s = lv1B[tid];
        for (int k = 0; k < DD; k++)
            s = fmaf(p[k], lv1W[(size_t)k * 256 + tid], s);
        hb[tid] = fmaxf(s, 0.f);
    }
    __syncthreads();
    if (tid < LAT) {
        float s = lv2B[tid];
        for (int k = 0; k < 2 * LAT; k++)
            s = fmaf(hb[k], lv2W[(size_t)k * LAT + tid], s);
        lv[b * LAT + tid] = s;
    }
}

// ---------------- launch -----------------------------------------------------
extern "C" void kernel_launch(void* const* d_in, const int* in_sizes, int n_in,
                              void* d_out, int out_size)
{
    const float* feats  = (const float*)d_in[0];
    const float* projW  = (const float*)d_in[1];
    const float* projB  = (const float*)d_in[2];
    const float* posenc = (const float*)d_in[3];
    const float* qkvW   = (const float*)d_in[4];
    const float* qkvB   = (const float*)d_in[5];
    const float* outW   = (const float*)d_in[6];
    const float* outB   = (const float*)d_in[7];
    const float* ln1s   = (const float*)d_in[8];
    const float* ln1b   = (const float*)d_in[9];
    const float* ff1W   = (const float*)d_in[10];
    const float* ff1B   = (const float*)d_in[11];
    const float* ff2W   = (const float*)d_in[12];
    const float* ff2B   = (const float*)d_in[13];
    const float* ln2s   = (const float*)d_in[14];
    const float* ln2b   = (const float*)d_in[15];
    const float* mu1W   = (const float*)d_in[16];
    const float* mu1B   = (const float*)d_in[17];
    const float* mu2W   = (const float*)d_in[18];
    const float* mu2B   = (const float*)d_in[19];
    const float* lv1W   = (const float*)d_in[20];
    const float* lv1B   = (const float*)d_in[21];
    const float* lv2W   = (const float*)d_in[22];
    const float* lv2B   = (const float*)d_in[23];

    float *ppool, *ppp;
    __half *pxh, *ptmph, *pqkvh, *pctxh, *pffh, *pfh;
    uint32_t* pwh;
    cudaGetSymbolAddress((void**)&ppool, g_pool);
    cudaGetSymbolAddress((void**)&ppp,   g_pp);
    cudaGetSymbolAddress((void**)&pxh,   g_xh);
    cudaGetSymbolAddress((void**)&ptmph, g_tmph);
    cudaGetSymbolAddress((void**)&pqkvh, g_qkvh);
    cudaGetSymbolAddress((void**)&pctxh, g_ctxh);
    cudaGetSymbolAddress((void**)&pffh,  g_ffh);
    cudaGetSymbolAddress((void**)&pfh,   g_fh);
    cudaGetSymbolAddress((void**)&pwh,   g_wh);

    cudaFuncSetAttribute(gemm_h<1>, cudaFuncAttributeMaxDynamicSharedMemorySize, GH_SMEM);
    cudaFuncSetAttribute(gemm_h<2>, cudaFuncAttributeMaxDynamicSharedMemorySize, GH_SMEM);
    cudaFuncSetAttribute(gemm_h<3>, cudaFuncAttributeMaxDynamicSharedMemorySize, GH_SMEM);
    cudaFuncSetAttribute(gemm_h<5>, cudaFuncAttributeMaxDynamicSharedMemorySize, GH_SMEM);
    cudaFuncSetAttribute(attn_h,    cudaFuncAttributeMaxDynamicSharedMemorySize, ATTN_SMEM);

    float* emb = (float*)d_out;
    float* mu  = emb + (size_t)ROWS * DD;
    float* lv  = mu + BB * LAT;

    // fused prep: feats conv + all weight packing (1 launch)
    {
        const long total = FH_W + WH_TOT;
        prep_all<<<(unsigned)((total + 255) / 256), 256>>>(feats, projW, qkvW, outW,
                                                           ff1W, ff2W, pfh, pwh);
    }

    // x = feats @ projW + projB + posenc  (half)
    gemm_h<2><<<dim3(4, 64), 256, GH_SMEM>>>(pfh, pwh + WH_PROJ, projB, posenc,
                                             nullptr, pxh, 512, 64);

    for (int l = 0; l < LL; l++) {
        gemm_h<3><<<dim3(12, 64), 256, GH_SMEM>>>(pxh, pwh + WH_QKV + (size_t)l * 393216,
                                                  qkvB + l * 3 * DD, nullptr, nullptr,
                                                  pqkvh, 1536, 512);
        attn_h<<<BB * HH * 16, 256, ATTN_SMEM>>>(pqkvh, pctxh);
        gemm_h<5><<<dim3(4, 64), 256, GH_SMEM>>>(pctxh, pwh + WH_OUT + (size_t)l * 131072,
                                                 outB + l * DD, nullptr, pxh,
                                                 ptmph, 512, 512);
        ln_h<0><<<ROWS / 8, 256>>>(ptmph, ln1s + l * DD, ln1b + l * DD, nullptr, pxh);
        gemm_h<1><<<dim3(16, 64), 256, GH_SMEM>>>(pxh, pwh + WH_FF1 + (size_t)l * 524288,
                                                  ff1B + l * FF_, nullptr, nullptr,
                                                  pffh, 2048, 512);
        gemm_h<5><<<dim3(4, 64), 256, GH_SMEM>>>(pffh, pwh + WH_FF2 + (size_t)l * 524288,
                                                 ff2B + l * DD, nullptr, pxh,
                                                 ptmph, 512, 2048);
        if (l == LL - 1)
            ln_h<1><<<ROWS / 8, 256>>>(ptmph, ln2s + l * DD, ln2b + l * DD, emb, nullptr);
        else
            ln_h<0><<<ROWS / 8, 256>>>(ptmph, ln2s + l * DD, ln2b + l * DD, nullptr, pxh);
    }

    pool_partial<<<BB * 32, DD>>>(emb, ppp);
    heads<<<BB, 256>>>(ppp, mu1W, mu1B, mu2W, mu2B, lv1W, lv1B, lv2W, lv2B, mu, lv);
}